// round 5
// baseline (speedup 1.0000x reference)
#include <cuda_runtime.h>
#include <cuda_bf16.h>
#include <cstdint>

// VectorQuantizer: x [32,2048,64] f32, codebook [1024,64] f32
// out f32: quantized [32,64,2048] | loss | indices [32,2048]

#define N_TOK   (32 * 2048)
#define K_CODES 1024
#define D_DIM   64
#define T_LEN   2048
#define LOSS_OFF ((size_t)N_TOK * D_DIM)       // 4194304
#define IDX_OFF  (LOSS_OFF + 1)                // 4194305
#define DELTA    8e-5f

#define M_CTA   128
#define N_CH    64                              // codes per chunk
#define NCH     (K_CODES / N_CH)                // 16
#define PADK    72                              // padded bf16 row stride (144B)

// dynamic smem layout (bytes)
#define SM_XH    0                              // 128 x 72 bf16 = 18432
#define SM_XL    18432
#define SM_EH(b) (36864 + (b) * 18432)          // 64 x 72 bf16 = 9216 (h then l)
#define SM_EL(b) (SM_EH(b) + 9216)
#define SM_BSQ   73728                          // 1024 f32
#define SM_IDX   77824                          // 128 i32
#define SMEM_TOTAL 78336

__device__ double g_loss_acc;
__device__ float  g_bsq[K_CODES];
__device__ int    g_flag_cnt;
__device__ int    g_flags[N_TOK];
__device__ __nv_bfloat16 g_xh[(size_t)N_TOK * D_DIM];
__device__ __nv_bfloat16 g_xl[(size_t)N_TOK * D_DIM];
__device__ __nv_bfloat16 g_eh[K_CODES * D_DIM];
__device__ __nv_bfloat16 g_el[K_CODES * D_DIM];

#define CP_ASYNC16(dst, src) \
    asm volatile("cp.async.cg.shared.global [%0], [%1], 16;" \
        :: "r"(dst), "l"(__cvta_generic_to_global(src)) : "memory")
#define CP_COMMIT() asm volatile("cp.async.commit_group;" ::: "memory")
#define CP_WAIT(n)  asm volatile("cp.async.wait_group %0;" :: "n"(n) : "memory")

// mma.sync m16n8k16 bf16 (baseline ISA, works on compute_103)
#define MMA_BF16(c, a, b0, b1) \
    asm volatile("mma.sync.aligned.m16n8k16.row.col.f32.bf16.bf16.f32 " \
        "{%0,%1,%2,%3}, {%4,%5,%6,%7}, {%8,%9}, {%0,%1,%2,%3};" \
        : "+f"((c)[0]), "+f"((c)[1]), "+f"((c)[2]), "+f"((c)[3]) \
        : "r"((a)[0]), "r"((a)[1]), "r"((a)[2]), "r"((a)[3]), "r"(b0), "r"(b1))

__device__ __forceinline__ uint32_t smem_u32(const void* p) {
    uint32_t a;
    asm("{ .reg .u64 t; cvta.to.shared.u64 t, %1; cvt.u32.u64 %0, t; }" : "=r"(a) : "l"(p));
    return a;
}

// ---------------- prep / misc kernels ----------------
__global__ void vq_init_kernel() { g_loss_acc = 0.0; g_flag_cnt = 0; }

__global__ void vq_prep_x_kernel(const float* __restrict__ x) {
    int i = blockIdx.x * blockDim.x + threadIdx.x;
    float f = x[i];
    __nv_bfloat16 h = __float2bfloat16(f);
    g_xh[i] = h;
    g_xl[i] = __float2bfloat16(__fadd_rn(f, -__bfloat162float(h)));
}

__global__ void vq_prep_e_kernel(const float* __restrict__ cb) {
    int i = blockIdx.x * blockDim.x + threadIdx.x;
    float v = __fmul_rn(-2.0f, cb[i]);            // exact (x2 power of two)
    __nv_bfloat16 h = __float2bfloat16(v);
    g_eh[i] = h;
    g_el[i] = __float2bfloat16(__fadd_rn(v, -__bfloat162float(h)));
}

// B_k = sum(e_k^2), sequential fp32 mul-then-add (reference rounding)
__global__ void vq_bsq_kernel(const float* __restrict__ cb) {
    int k = blockIdx.x * blockDim.x + threadIdx.x;
    if (k >= K_CODES) return;
    float s = 0.0f;
    const float* row = cb + (size_t)k * D_DIM;
    #pragma unroll 8
    for (int i = 0; i < D_DIM; i++) s = __fadd_rn(s, __fmul_rn(row[i], row[i]));
    g_bsq[k] = s;
}

// ---------------- main HMMA kernel ----------------
__global__ __launch_bounds__(128, 2) void vq_hmma_kernel(
    const float* __restrict__ x, const float* __restrict__ cb, float* __restrict__ out)
{
    extern __shared__ char smem[];
    const uint32_t sb = smem_u32(smem);
    const int tid  = threadIdx.x;
    const int w    = tid >> 5;
    const int lane = tid & 31;
    const int g    = lane >> 2;       // group id (rows / B-cols)
    const int q    = lane & 3;        // thread-in-group (k pairs / C-cols)
    const int blk0 = blockIdx.x * M_CTA;

    // ---- prologue copies: G0 = x tiles + bsq + E chunk0 ; G1 = E chunk1 ----
    #pragma unroll
    for (int u = tid; u < M_CTA * 8; u += 128) {
        int row = u >> 3, s = u & 7;
        uint32_t off = (uint32_t)(row * (PADK * 2) + s * 16);
        CP_ASYNC16(sb + SM_XH + off, g_xh + (size_t)(blk0 + row) * 64 + s * 8);
        CP_ASYNC16(sb + SM_XL + off, g_xl + (size_t)(blk0 + row) * 64 + s * 8);
    }
    #pragma unroll
    for (int u = tid; u < 256; u += 128)
        CP_ASYNC16(sb + SM_BSQ + u * 16, (const char*)g_bsq + u * 16);
    #pragma unroll
    for (int u = tid; u < N_CH * 8; u += 128) {
        int row = u >> 3, s = u & 7;
        uint32_t off = (uint32_t)(row * (PADK * 2) + s * 16);
        CP_ASYNC16(sb + SM_EH(0) + off, g_eh + (size_t)row * 64 + s * 8);
        CP_ASYNC16(sb + SM_EL(0) + off, g_el + (size_t)row * 64 + s * 8);
    }
    CP_COMMIT();
    #pragma unroll
    for (int u = tid; u < N_CH * 8; u += 128) {
        int row = u >> 3, s = u & 7;
        uint32_t off = (uint32_t)(row * (PADK * 2) + s * 16);
        CP_ASYNC16(sb + SM_EH(1) + off, g_eh + (size_t)(N_CH + row) * 64 + s * 8);
        CP_ASYNC16(sb + SM_EL(1) + off, g_el + (size_t)(N_CH + row) * 64 + s * 8);
    }
    CP_COMMIT();

    CP_WAIT(1);
    __syncthreads();                  // x, bsq, E0 visible

    // ---- load A fragments (resident): xh/xl, M=32 per warp, K=64 ----
    uint32_t ah[2][4][4], al[2][4][4];
    {
        const char* pxh = smem + SM_XH;
        const char* pxl = smem + SM_XL;
        #pragma unroll
        for (int mt = 0; mt < 2; mt++) {
            int r0 = w * 32 + mt * 16 + g;
            #pragma unroll
            for (int ks = 0; ks < 4; ks++) {
                int c0 = ks * 16 + q * 2;
                ah[mt][ks][0] = *(const uint32_t*)(pxh + (r0 * PADK + c0) * 2);
                ah[mt][ks][1] = *(const uint32_t*)(pxh + ((r0 + 8) * PADK + c0) * 2);
                ah[mt][ks][2] = *(const uint32_t*)(pxh + (r0 * PADK + c0 + 8) * 2);
                ah[mt][ks][3] = *(const uint32_t*)(pxh + ((r0 + 8) * PADK + c0 + 8) * 2);
                al[mt][ks][0] = *(const uint32_t*)(pxl + (r0 * PADK + c0) * 2);
                al[mt][ks][1] = *(const uint32_t*)(pxl + ((r0 + 8) * PADK + c0) * 2);
                al[mt][ks][2] = *(const uint32_t*)(pxl + (r0 * PADK + c0 + 8) * 2);
                al[mt][ks][3] = *(const uint32_t*)(pxl + ((r0 + 8) * PADK + c0 + 8) * 2);
            }
        }
    }

    // top-2 per local row (lr = mt*2 + upper-half)
    float m1[4] = {3.4e38f, 3.4e38f, 3.4e38f, 3.4e38f};
    float m2[4] = {3.4e38f, 3.4e38f, 3.4e38f, 3.4e38f};
    int   i1[4] = {0, 0, 0, 0};

    for (int ch = 0; ch < NCH; ch++) {
        CP_WAIT(1);
        __syncthreads();              // E_ch ready in buf[ch&1]

        // ---- acc init with B_k: value will be B_k - 2*dot ----
        float c[2][8][4];
        {
            const float* sBp = (const float*)(smem + SM_BSQ) + ch * N_CH + q * 2;
            #pragma unroll
            for (int nt = 0; nt < 8; nt++) {
                float2 bv = *(const float2*)(sBp + nt * 8);
                #pragma unroll
                for (int mt = 0; mt < 2; mt++) {
                    c[mt][nt][0] = bv.x; c[mt][nt][1] = bv.y;
                    c[mt][nt][2] = bv.x; c[mt][nt][3] = bv.y;
                }
            }
        }

        // ---- 3-pass split-bf16 MMA ----
        const char* peh = smem + SM_EH(ch & 1);
        const char* pel = smem + SM_EL(ch & 1);
        #pragma unroll
        for (int ks = 0; ks < 4; ks++) {
            int kc = ks * 16 + q * 2;
            #pragma unroll
            for (int nt = 0; nt < 8; nt++) {
                int n = nt * 8 + g;
                uint32_t bh0 = *(const uint32_t*)(peh + (n * PADK + kc) * 2);
                uint32_t bh1 = *(const uint32_t*)(peh + (n * PADK + kc + 8) * 2);
                uint32_t bl0 = *(const uint32_t*)(pel + (n * PADK + kc) * 2);
                uint32_t bl1 = *(const uint32_t*)(pel + (n * PADK + kc + 8) * 2);
                MMA_BF16(c[0][nt], ah[0][ks], bh0, bh1);
                MMA_BF16(c[1][nt], ah[1][ks], bh0, bh1);
                MMA_BF16(c[0][nt], ah[0][ks], bl0, bl1);
                MMA_BF16(c[1][nt], ah[1][ks], bl0, bl1);
                MMA_BF16(c[0][nt], al[0][ks], bh0, bh1);
                MMA_BF16(c[1][nt], al[1][ks], bh0, bh1);
            }
        }

        // ---- top-2 scan of this chunk ----
        int kb = ch * N_CH + q * 2;
        #pragma unroll
        for (int mt = 0; mt < 2; mt++)
            #pragma unroll
            for (int nt = 0; nt < 8; nt++)
                #pragma unroll
                for (int h = 0; h < 2; h++) {
                    int lr = mt * 2 + h;
                    #pragma unroll
                    for (int e = 0; e < 2; e++) {
                        float v = c[mt][nt][h * 2 + e];
                        int   k = kb + nt * 8 + e;
                        if (v < m1[lr]) { m2[lr] = m1[lr]; m1[lr] = v; i1[lr] = k; }
                        else if (v < m2[lr]) m2[lr] = v;
                    }
                }

        __syncthreads();              // all warps done reading buf[ch&1]
        if (ch + 2 < NCH) {
            #pragma unroll
            for (int u = tid; u < N_CH * 8; u += 128) {
                int row = u >> 3, s = u & 7;
                uint32_t off = (uint32_t)(row * (PADK * 2) + s * 16);
                CP_ASYNC16(sb + SM_EH(ch & 1) + off, g_eh + (size_t)((ch + 2) * N_CH + row) * 64 + s * 8);
                CP_ASYNC16(sb + SM_EL(ch & 1) + off, g_el + (size_t)((ch + 2) * N_CH + row) * 64 + s * 8);
            }
            CP_COMMIT();
        }
    }

    // ---- merge top-2 across the quad (lanes sharing the same rows) ----
    #pragma unroll
    for (int off = 1; off < 4; off <<= 1) {
        #pragma unroll
        for (int lr = 0; lr < 4; lr++) {
            float om1 = __shfl_xor_sync(0xffffffffu, m1[lr], off);
            float om2 = __shfl_xor_sync(0xffffffffu, m2[lr], off);
            int   oi1 = __shfl_xor_sync(0xffffffffu, i1[lr], off);
            if (om1 < m1[lr]) {
                m2[lr] = fminf(m1[lr], om2);
                m1[lr] = om1; i1[lr] = oi1;
            } else {
                m2[lr] = fminf(m2[lr], om1);
            }
        }
    }
    int* s_idx = (int*)(smem + SM_IDX);
    if (q == 0) {
        #pragma unroll
        for (int lr = 0; lr < 4; lr++) {
            int mt = lr >> 1, h = lr & 1;
            int row = w * 32 + mt * 16 + g + h * 8;
            bool flagged = (m2[lr] < m1[lr] + DELTA);
            s_idx[row] = flagged ? -1 : i1[lr];
        }
    }
    __syncthreads();

    // ---- epilogue (one token per thread, coalesced along t) ----
    const int tok = blk0 + tid;
    const int myidx = s_idx[tid];
    double ls = 0.0;
    if (myidx < 0) {
        int pos = atomicAdd(&g_flag_cnt, 1);
        g_flags[pos] = tok;
    } else {
        const int bq = tok >> 11, tq = tok & 2047;
        float* qout = out + ((size_t)bq * D_DIM) * T_LEN + tq;
        const float* xr = x + (size_t)tok * D_DIM;
        const float* er = cb + (size_t)myidx * D_DIM;
        #pragma unroll
        for (int i = 0; i < D_DIM; i++) {
            float xv = xr[i];
            float dv = __fadd_rn(er[i], -xv);
            ls += (double)dv * dv;
            qout[(size_t)i * T_LEN] = __fadd_rn(xv, dv);
        }
        out[IDX_OFF + tok] = (float)myidx;
    }
    #pragma unroll
    for (int o = 16; o > 0; o >>= 1)
        ls += __shfl_down_sync(0xffffffffu, ls, o);
    if ((tid & 31) == 0 && ls != 0.0) atomicAdd(&g_loss_acc, ls);
}

// ---------------- exact repair kernel (flagged tokens, R1-bitwise) ----------------
#define EX_GRID 512
__global__ __launch_bounds__(128) void vq_exact_kernel(
    const float* __restrict__ x, const float* __restrict__ cb, float* __restrict__ out)
{
    const int cnt = g_flag_cnt;
    if (blockIdx.x * 8 >= cnt) return;
    __shared__ float sx[8][D_DIM];
    __shared__ int   stok[8];
    const int g = threadIdx.x >> 4, c = threadIdx.x & 15;

    for (int base = blockIdx.x * 8; base < cnt; base += EX_GRID * 8) {
        __syncthreads();
        int slot = base + g;
        if (c == 0) stok[g] = (slot < cnt) ? g_flags[slot] : -1;
        __syncthreads();
        int tok = stok[g];
        if (tok >= 0) {
            #pragma unroll
            for (int i = 0; i < 4; i++) sx[g][c * 4 + i] = x[(size_t)tok * D_DIM + c * 4 + i];
        }
        __syncthreads();

        float best = 3.402823466e38f; int bidx = 0;
        if (tok >= 0) {
            float A = 0.0f;
            #pragma unroll
            for (int i = 0; i < D_DIM; i++) A = __fadd_rn(A, __fmul_rn(sx[g][i], sx[g][i]));
            for (int t = 0; t < K_CODES / 16; t++) {
                int k = c + 16 * t;                 // ascending per lane
                const float* e = cb + (size_t)k * D_DIM;
                float a0 = 0.f, a1 = 0.f, a2 = 0.f, a3 = 0.f;
                #pragma unroll
                for (int j = 0; j < 16; j++) {      // R1's exact mod-4 chains
                    a0 = fmaf(sx[g][4 * j + 0], e[4 * j + 0], a0);
                    a1 = fmaf(sx[g][4 * j + 1], e[4 * j + 1], a1);
                    a2 = fmaf(sx[g][4 * j + 2], e[4 * j + 2], a2);
                    a3 = fmaf(sx[g][4 * j + 3], e[4 * j + 3], a3);
                }
                float dot = __fadd_rn(__fadd_rn(a0, a1), __fadd_rn(a2, a3));
                float tv  = __fadd_rn(A, g_bsq[k]);
                float d   = __fadd_rn(tv, -__fmul_rn(2.0f, dot));
                if (d < best) { best = d; bidx = k; }
            }
        }
        // lex argmin across the 16-lane group (first-index tie-break)
        #pragma unroll
        for (int o = 8; o > 0; o >>= 1) {
            float ob = __shfl_down_sync(0xffffffffu, best, o, 16);
            int   oi = __shfl_down_sync(0xffffffffu, bidx, o, 16);
            if (ob < best || (ob == best && oi < bidx)) { best = ob; bidx = oi; }
        }
        if (tok >= 0 && c == 0) {
            const int bq = tok >> 11, tq = tok & 2047;
            float* qout = out + ((size_t)bq * D_DIM) * T_LEN + tq;
            const float* er = cb + (size_t)bidx * D_DIM;
            double ls = 0.0;
            #pragma unroll
            for (int i = 0; i < D_DIM; i++) {
                float xv = sx[g][i];
                float dv = __fadd_rn(er[i], -xv);
                ls += (double)dv * dv;
                qout[(size_t)i * T_LEN] = __fadd_rn(xv, dv);
            }
            out[IDX_OFF + tok] = (float)bidx;
            atomicAdd(&g_loss_acc, ls);
        }
    }
}

__global__ void vq_finalize_kernel(float* __restrict__ out) {
    double m = g_loss_acc / (double)((size_t)N_TOK * D_DIM);
    out[LOSS_OFF] = (float)(m + 0.25 * m);
}

extern "C" void kernel_launch(void* const* d_in, const int* in_sizes, int n_in,
                              void* d_out, int out_size) {
    const float* x  = (const float*)d_in[0];
    const float* cb = (const float*)d_in[1];
    float* out = (float*)d_out;
    (void)in_sizes; (void)n_in; (void)out_size;

    cudaFuncSetAttribute(vq_hmma_kernel, cudaFuncAttributeMaxDynamicSharedMemorySize, SMEM_TOTAL);

    vq_init_kernel<<<1, 1>>>();
    vq_prep_x_kernel<<<(N_TOK * D_DIM) / 256, 256>>>(x);
    vq_prep_e_kernel<<<(K_CODES * D_DIM) / 256, 256>>>(cb);
    vq_bsq_kernel<<<8, 128>>>(cb);
    vq_hmma_kernel<<<N_TOK / M_CTA, 128, SMEM_TOTAL>>>(x, cb, out);
    vq_exact_kernel<<<EX_GRID, 128>>>(x, cb, out);
    vq_finalize_kernel<<<1, 1>>>(out);
}